// round 3
// baseline (speedup 1.0000x reference)
#include <cuda_runtime.h>
#include <math.h>

#define HWSZ 12544      // 112*112
#define IMGW 112
#define NB   16
#define EPSV 1e-5f

// ---- scratch (tiny) ----
__device__ float g_pooled[NB * 64];
__device__ float g_sum1[NB * 64];      // post-act x1 channel sums
__device__ float g_sum2[NB * 64];      // post-act x2 channel sums
__device__ float g_gates[NB * 128];

__device__ __forceinline__ float sigmoidf_(float x) { return 1.f / (1.f + expf(-x)); }

// ---- mean over HW per (b,c) + zero sums: grid 1024 x 256 ----
__global__ __launch_bounds__(256) void pool1_kernel(const float* __restrict__ x) {
    int bc = blockIdx.x;
    if (threadIdx.x == 0) { g_sum1[bc] = 0.f; g_sum2[bc] = 0.f; }
    const float4* p = (const float4*)(x + (size_t)bc * HWSZ);
    float s = 0.f;
    for (int i = threadIdx.x; i < HWSZ / 4; i += 256) {
        float4 v = p[i];
        s += v.x + v.y + v.z + v.w;
    }
    for (int o = 16; o; o >>= 1) s += __shfl_xor_sync(0xffffffffu, s, o);
    __shared__ float red[8];
    if ((threadIdx.x & 31) == 0) red[threadIdx.x >> 5] = s;
    __syncthreads();
    if (threadIdx.x < 8) {
        s = red[threadIdx.x];
        for (int o = 4; o; o >>= 1) s += __shfl_xor_sync(0xffu, s, o);
        if (threadIdx.x == 0) g_pooled[bc] = s * (1.f / (float)HWSZ);
    }
}

// ---- dynamic 1x1 conv, k1 built in-smem + BN + ReLU + channel-sum ----
// tile: 64 outputs x 256 pixels; per lane 8 out x 8 px. grid (49, NB) x 256
extern __shared__ float conv1_smem[];
__global__ __launch_bounds__(256, 2) void conv1_kernel(
    const float* __restrict__ x,
    const float* __restrict__ rw1, const float* __restrict__ rb1,
    const float* __restrict__ w1,
    const float* __restrict__ g1, const float* __restrict__ b1,
    const float* __restrict__ m1, const float* __restrict__ v1,
    float* __restrict__ out) {
    float* ks = conv1_smem;          // [64i][64o] = 4096
    float* xs = conv1_smem + 4096;   // [64i][256px] = 16384
    __shared__ float r1s[4];
    int b = blockIdx.y;
    int p0 = blockIdx.x * 256;
    int tid = threadIdx.x;

    {
        float4* xdst = (float4*)xs;
#pragma unroll
        for (int i = 0; i < 16; i++) {
            int idx = tid + 256 * i;           // f4 index in [0,4096)
            int row = idx >> 6, col = (idx & 63) << 2;
            xdst[idx] = *(const float4*)&x[((size_t)(b * 64 + row)) * HWSZ + p0 + col];
        }
    }
    if (tid < 4) {
        float a = rb1[tid];
        for (int i = 0; i < 64; i++) a += g_pooled[b * 64 + i] * rw1[tid * 64 + i];
        r1s[tid] = sigmoidf_(a);
    }
    __syncthreads();
    // build mixed 1x1 kernel in smem, layout [i][o], BN1 scale folded
#pragma unroll
    for (int k = 0; k < 16; k++) {
        int idx = tid + 256 * k;
        int i = idx >> 6, o = idx & 63;
        float a = 0.f;
#pragma unroll
        for (int e = 0; e < 4; e++) a += r1s[e] * __ldg(&w1[e * 4096 + o * 64 + i]);
        ks[idx] = a * (g1[o] * rsqrtf(v1[o] + EPSV));
    }
    __syncthreads();

    int og = (tid >> 5) << 3;    // warp -> 8 outputs
    int q0 = (tid & 31) << 2;    // lane -> px [q0..q0+3] and [q0+128..q0+131]
    float acc[8][8];
#pragma unroll
    for (int a = 0; a < 8; a++)
#pragma unroll
        for (int p = 0; p < 8; p++) acc[a][p] = 0.f;

#pragma unroll 8
    for (int i = 0; i < 64; i++) {
        float4 xa = *(const float4*)&xs[(i << 8) + q0];
        float4 xb = *(const float4*)&xs[(i << 8) + 128 + q0];
        float4 ka = *(const float4*)&ks[(i << 6) + og];
        float4 kb = *(const float4*)&ks[(i << 6) + og + 4];
        float kr[8] = {ka.x, ka.y, ka.z, ka.w, kb.x, kb.y, kb.z, kb.w};
        float xr[8] = {xa.x, xa.y, xa.z, xa.w, xb.x, xb.y, xb.z, xb.w};
#pragma unroll
        for (int a = 0; a < 8; a++)
#pragma unroll
            for (int p = 0; p < 8; p++) acc[a][p] = fmaf(kr[a], xr[p], acc[a][p]);
    }

#pragma unroll
    for (int a = 0; a < 8; a++) {
        int o = og + a;
        float sc = g1[o] * rsqrtf(v1[o] + EPSV);
        float sh = b1[o] - m1[o] * sc;
        float4 r0, r1q;
        r0.x = fmaxf(acc[a][0] + sh, 0.f);
        r0.y = fmaxf(acc[a][1] + sh, 0.f);
        r0.z = fmaxf(acc[a][2] + sh, 0.f);
        r0.w = fmaxf(acc[a][3] + sh, 0.f);
        r1q.x = fmaxf(acc[a][4] + sh, 0.f);
        r1q.y = fmaxf(acc[a][5] + sh, 0.f);
        r1q.z = fmaxf(acc[a][6] + sh, 0.f);
        r1q.w = fmaxf(acc[a][7] + sh, 0.f);
        float* op = out + ((size_t)(b * 128 + o)) * HWSZ + p0;
        *(float4*)&op[q0] = r0;
        *(float4*)&op[128 + q0] = r1q;
        float s = r0.x + r0.y + r0.z + r0.w + r1q.x + r1q.y + r1q.z + r1q.w;
        for (int o2 = 16; o2; o2 >>= 1) s += __shfl_xor_sync(0xffffffffu, s, o2);
        if ((tid & 31) == 0) atomicAdd(&g_sum1[b * 64 + o], s);
    }
}

// ---- dynamic 3x3 depthwise pass over one whole channel per block ----
// MODE 0: compute relu(dw) channel sums only (no stores)
// MODE 1: write gated x1 (in place) + gated x2 (recomputed dw)
// grid 1024, block 224, dyn smem = 112*120 floats
#define DWST 120
template <int STORE>
__global__ __launch_bounds__(224) void dw_pass_kernel(
    const float* __restrict__ rw2, const float* __restrict__ rb2,
    const float* __restrict__ w2,
    const float* __restrict__ g2, const float* __restrict__ b2,
    const float* __restrict__ m2, const float* __restrict__ v2,
    float* __restrict__ out) {
    extern __shared__ float sm[];     // [112 rows][120]
    __shared__ float r2s[4];
    __shared__ float kk[9];
    __shared__ float shb, g1c_s, g2c_s;
    __shared__ float red[7];

    int bc = blockIdx.x;
    int b = bc >> 6, c = bc & 63;
    float* ch1 = out + ((size_t)(b * 128 + c)) * HWSZ;
    float* ch2 = out + ((size_t)(b * 128 + 64 + c)) * HWSZ;
    int tid = threadIdx.x;

    // load whole channel: 3136 f4 with 224 threads = 14 each
#pragma unroll
    for (int k = 0; k < 14; k++) {
        int i = tid + 224 * k;
        int r = i / 28, q = i % 28;
        *(float4*)&sm[r * DWST + 4 + q * 4] = *(const float4*)&ch1[r * IMGW + q * 4];
    }
    for (int r = tid; r < IMGW; r += 224) { sm[r * DWST + 3] = 0.f; sm[r * DWST + 116] = 0.f; }
    if (tid < 4) {
        float a = rb2[tid];
        for (int cc = 0; cc < 64; cc++)
            a += g_sum1[b * 64 + cc] * (1.f / (float)HWSZ) * rw2[tid * 64 + cc];
        r2s[tid] = sigmoidf_(a);
    }
    if (STORE && tid == 4) {
        g1c_s = g_gates[b * 128 + c];
        g2c_s = g_gates[b * 128 + 64 + c];
    }
    __syncthreads();
    if (tid < 9) {
        float a = 0.f;
#pragma unroll
        for (int e = 0; e < 4; e++) a += r2s[e] * w2[e * 576 + c * 9 + tid];
        kk[tid] = a * (g2[c] * rsqrtf(v2[c] + EPSV));
    }
    if (tid == 9) {
        float sc = g2[c] * rsqrtf(v2[c] + EPSV);
        shb = b2[c] - m2[c] * sc;
    }
    __syncthreads();

    int q = tid % 28, rr = tid / 28;
    int xb = 4 + q * 4;
    float bias = shb;
    float g1c = STORE ? g1c_s : 0.f;
    float g2c = STORE ? g2c_s : 0.f;
    float tsum = 0.f;

#pragma unroll 2
    for (int j = 0; j < 14; j++) {
        int y = rr + 8 * j;
        float a0 = bias, a1 = bias, a2 = bias, a3 = bias;
        float4 mid = make_float4(0.f, 0.f, 0.f, 0.f);
#pragma unroll
        for (int dr = -1; dr <= 1; dr++) {
            int yy = y + dr;
            if ((unsigned)yy < (unsigned)IMGW) {
                const float* row = &sm[yy * DWST];
                float l = row[xb - 1];
                float4 m = *(const float4*)&row[xb];
                float rt = row[xb + 4];
                if (dr == 0) mid = m;
                float k0 = kk[(dr + 1) * 3 + 0], k1 = kk[(dr + 1) * 3 + 1], k2 = kk[(dr + 1) * 3 + 2];
                a0 = fmaf(k0, l,   fmaf(k1, m.x, fmaf(k2, m.y, a0)));
                a1 = fmaf(k0, m.x, fmaf(k1, m.y, fmaf(k2, m.z, a1)));
                a2 = fmaf(k0, m.y, fmaf(k1, m.z, fmaf(k2, m.w, a2)));
                a3 = fmaf(k0, m.z, fmaf(k1, m.w, fmaf(k2, rt, a3)));
            }
        }
        float4 r;
        r.x = fmaxf(a0, 0.f); r.y = fmaxf(a1, 0.f);
        r.z = fmaxf(a2, 0.f); r.w = fmaxf(a3, 0.f);
        if (STORE) {
            float4 o2 = make_float4(r.x * g2c, r.y * g2c, r.z * g2c, r.w * g2c);
            *(float4*)&ch2[y * IMGW + q * 4] = o2;
            float4 o1 = make_float4(mid.x * g1c, mid.y * g1c, mid.z * g1c, mid.w * g1c);
            *(float4*)&ch1[y * IMGW + q * 4] = o1;
        } else {
            tsum += r.x + r.y + r.z + r.w;
        }
    }

    if (!STORE) {
        for (int o = 16; o; o >>= 1) tsum += __shfl_xor_sync(0xffffffffu, tsum, o);
        if ((tid & 31) == 0) red[tid >> 5] = tsum;
        __syncthreads();
        if (tid < 7) {
            float s = red[tid];
            for (int o = 4; o; o >>= 1) s += __shfl_xor_sync(0x7fu, s, o);
            if (tid == 0) atomicAdd(&g_sum2[bc], s);
        }
    }
}

// ---- SE MLP -> gates: grid NB x 128 ----
__global__ __launch_bounds__(128) void se_kernel(
    const float* __restrict__ sw1, const float* __restrict__ sb1,
    const float* __restrict__ sw2, const float* __restrict__ sb2) {
    int b = blockIdx.x;
    int tid = threadIdx.x;
    __shared__ float sm[128];
    __shared__ float h[32];
    sm[tid] = (tid < 64 ? g_sum1[b * 64 + tid] : g_sum2[b * 64 + tid - 64]) * (1.f / (float)HWSZ);
    __syncthreads();
    if (tid < 32) {
        float a = sb1[tid];
        for (int c = 0; c < 128; c++) a += sw1[tid * 128 + c] * sm[c];
        h[tid] = fmaxf(a, 0.f);
    }
    __syncthreads();
    float a = sb2[tid];
#pragma unroll
    for (int j = 0; j < 32; j++) a += sw2[tid * 32 + j] * h[j];
    g_gates[b * 128 + tid] = sigmoidf_(a);
}

// ---------------------------------------------------------------
extern "C" void kernel_launch(void* const* d_in, const int* in_sizes, int n_in,
                              void* d_out, int out_size) {
    const float* x    = (const float*)d_in[0];
    const float* rw1  = (const float*)d_in[1];
    const float* rb1  = (const float*)d_in[2];
    const float* w1   = (const float*)d_in[3];
    const float* bn1g = (const float*)d_in[4];
    const float* bn1b = (const float*)d_in[5];
    const float* bn1m = (const float*)d_in[6];
    const float* bn1v = (const float*)d_in[7];
    const float* rw2  = (const float*)d_in[8];
    const float* rb2  = (const float*)d_in[9];
    const float* w2   = (const float*)d_in[10];
    const float* bn2g = (const float*)d_in[11];
    const float* bn2b = (const float*)d_in[12];
    const float* bn2m = (const float*)d_in[13];
    const float* bn2v = (const float*)d_in[14];
    const float* sw1  = (const float*)d_in[15];
    const float* sb1  = (const float*)d_in[16];
    const float* sw2  = (const float*)d_in[17];
    const float* sb2  = (const float*)d_in[18];
    float* out = (float*)d_out;

    const int conv1_smem_bytes = (4096 + 16384) * sizeof(float);
    const int dw_smem_bytes = IMGW * DWST * sizeof(float);
    cudaFuncSetAttribute(conv1_kernel, cudaFuncAttributeMaxDynamicSharedMemorySize, conv1_smem_bytes);
    cudaFuncSetAttribute(dw_pass_kernel<0>, cudaFuncAttributeMaxDynamicSharedMemorySize, dw_smem_bytes);
    cudaFuncSetAttribute(dw_pass_kernel<1>, cudaFuncAttributeMaxDynamicSharedMemorySize, dw_smem_bytes);

    pool1_kernel<<<NB * 64, 256>>>(x);
    conv1_kernel<<<dim3(HWSZ / 256, NB), 256, conv1_smem_bytes>>>(
        x, rw1, rb1, w1, bn1g, bn1b, bn1m, bn1v, out);
    dw_pass_kernel<0><<<NB * 64, 224, dw_smem_bytes>>>(
        rw2, rb2, w2, bn2g, bn2b, bn2m, bn2v, out);
    se_kernel<<<NB, 128>>>(sw1, sb1, sw2, sb2);
    dw_pass_kernel<1><<<NB * 64, 224, dw_smem_bytes>>>(
        rw2, rb2, w2, bn2g, bn2b, bn2m, bn2v, out);
}